// round 14
// baseline (speedup 1.0000x reference)
#include <cuda_runtime.h>
#include <cuda_fp16.h>
#include <cstdint>

#define NLAYERS 2
#define NMAT 4
#define NE 9
#define D 128
#define NTOK 65536
#define TILE_M 128
#define NBLK (NTOK / TILE_M + NE)     // 521
#define NTHR 128

#define SLAB_U4 1024                   // uint4 per 16-col chunk slab
#define SMEM_TOTAL 4096                // biases only: 2 layers x 4 mats x 128 floats

// ---------------- device scratch ----------------
__device__ unsigned g_counts[NE];
__device__ unsigned g_list[NE * NTOK];             // per-expert arenas
// fragment-packed fp16 weights: [l][e][ch(8)][j(4)][ks(8)][lane(32)] uint4
__device__ uint4 g_Wp[NLAYERS * NE * 8 * NMAT * 8 * 32];

// ---------------- helpers ----------------
__device__ __forceinline__ float tanha(float v) {
    float r; asm("tanh.approx.f32 %0, %1;" : "=f"(r) : "f"(v)); return r;
}
__device__ __forceinline__ float sigm(float v) {
    return fmaf(0.5f, tanha(0.5f * v), 0.5f);
}
__device__ __forceinline__ uint32_t pkh2(float lo, float hi) {
    __half2 h = __floats2half2_rn(lo, hi);
    return *reinterpret_cast<uint32_t*>(&h);
}
__device__ __forceinline__ float2 uph2(uint32_t u) {
    __half2 h = *reinterpret_cast<__half2*>(&u);
    return __half22float2(h);
}
__device__ __forceinline__ void mma16(float* d, const uint32_t* a, uint32_t b0, uint32_t b1) {
    asm volatile(
        "mma.sync.aligned.m16n8k16.row.col.f32.f16.f16.f32 "
        "{%0,%1,%2,%3}, {%4,%5,%6,%7}, {%8,%9}, {%0,%1,%2,%3};"
        : "+f"(d[0]), "+f"(d[1]), "+f"(d[2]), "+f"(d[3])
        : "r"(a[0]), "r"(a[1]), "r"(a[2]), "r"(a[3]), "r"(b0), "r"(b1));
}
__device__ __forceinline__ uint4 ldg128nc(const uint4* p) {
    uint4 v;
    asm("ld.global.nc.v4.u32 {%0,%1,%2,%3}, [%4];"
        : "=r"(v.x), "=r"(v.y), "=r"(v.z), "=r"(v.w)
        : "l"(__cvta_generic_to_global(p)));
    return v;
}

// ---------------- prep kernels (2 launches) ----------------
__global__ void prep_pack(const float* __restrict__ W) {
    if (blockIdx.x == 0 && threadIdx.x < NE) g_counts[threadIdx.x] = 0;
    int i = blockIdx.x * blockDim.x + threadIdx.x;   // 147456 threads
    int lane = i & 31;
    int ks   = (i >> 5) & 7;
    int j    = (i >> 8) & 3;
    int ch   = (i >> 10) & 7;
    int i2   = i >> 13;
    int e    = i2 % NE;
    int l    = i2 / NE;
    int lk = lane & 3, ln = lane >> 2;
    const float* src = W + ((size_t)(l * NMAT + j) * NE + e) * (D * D);
    int k0 = ks * 16 + lk * 2;
    int colA = ch * 16 + ln;
    int colB = colA + 8;
    uint4 v;
    v.x = pkh2(src[(k0    ) * D + colA], src[(k0 + 1) * D + colA]);
    v.y = pkh2(src[(k0 + 8) * D + colA], src[(k0 + 9) * D + colA]);
    v.z = pkh2(src[(k0    ) * D + colB], src[(k0 + 1) * D + colB]);
    v.w = pkh2(src[(k0 + 8) * D + colB], src[(k0 + 9) * D + colB]);
    g_Wp[i] = v;
}
__global__ void prep_scatter(const int* __restrict__ pos) {
    __shared__ unsigned sc[NE];
    __shared__ unsigned sb[NE];
    if (threadIdx.x < NE) sc[threadIdx.x] = 0;
    __syncthreads();
    int t = blockIdx.x * blockDim.x + threadIdx.x;
    int e = min(pos[t], NE - 1);
    unsigned my = atomicAdd(&sc[e], 1u);
    __syncthreads();
    if (threadIdx.x < NE) sb[threadIdx.x] = atomicAdd(&g_counts[threadIdx.x], sc[threadIdx.x]);
    __syncthreads();
    g_list[(size_t)e * NTOK + sb[e] + my] = (unsigned)t;
}

// ---------------- per-layer body (no barriers; W straight from L1/L2) ----------------
template<int L>
__device__ __forceinline__ void do_layer(
    uint32_t (&xin)[4][8][2], uint32_t (&xout)[4][8][2],
    const float* Bs_all, int e,
    int lk, int row0, const unsigned* tokr, int vcnt,
    float* __restrict__ Out)
{
    const float* Bs = Bs_all + L * NMAT * D;
    const uint4* wl = g_Wp + (size_t)(L * NE + e) * 8 * SLAB_U4;

    #pragma unroll
    for (int ch = 0; ch < 8; ch++) {
        const uint4* wb = wl + ch * SLAB_U4 + (threadIdx.x & 31);

        float acc[4][2][2][4];
        #pragma unroll
        for (int m = 0; m < 4; m++)
            #pragma unroll
            for (int rt = 0; rt < 2; rt++)
                #pragma unroll
                for (int nt = 0; nt < 2; nt++)
                    #pragma unroll
                    for (int c = 0; c < 4; c++) acc[m][rt][nt][c] = 0.0f;

        #pragma unroll
        for (int ks = 0; ks < 8; ks++) {
            uint32_t a0[4] = { xin[0][ks][0], xin[1][ks][0], xin[0][ks][1], xin[1][ks][1] };
            uint32_t a1[4] = { xin[2][ks][0], xin[3][ks][0], xin[2][ks][1], xin[3][ks][1] };
            #pragma unroll
            for (int m = 0; m < 4; m++) {
                uint4 bq = ldg128nc(wb + (m * 8 + ks) * 32);
                mma16(acc[m][0][0], a0, bq.x, bq.y);
                mma16(acc[m][0][1], a0, bq.z, bq.w);
                mma16(acc[m][1][0], a1, bq.x, bq.y);
                mma16(acc[m][1][1], a1, bq.z, bq.w);
            }
        }

        // ---- gating (exact R11 form) ----
        float2 bv[4][2];
        #pragma unroll
        for (int m = 0; m < 4; m++)
            #pragma unroll
            for (int nt = 0; nt < 2; nt++)
                bv[m][nt] = *reinterpret_cast<const float2*>(
                    Bs + m * D + ch * 16 + nt * 8 + lk * 2);

        #pragma unroll
        for (int rt = 0; rt < 2; rt++) {
            #pragma unroll
            for (int h = 0; h < 2; h++) {
                int ri = rt * 2 + h;
                #pragma unroll
                for (int nt = 0; nt < 2; nt++) {
                    float2 xv = uph2(xin[ri][ch][nt]);
                    float v[2];
                    #pragma unroll
                    for (int c = 0; c < 2; c++) {
                        float sf = acc[0][rt][nt][h * 2 + c] + (&bv[0][nt].x)[c];
                        float lg = acc[1][rt][nt][h * 2 + c] + (&bv[1][nt].x)[c];
                        float lf = acc[2][rt][nt][h * 2 + c] + (&bv[2][nt].x)[c];
                        float of = acc[3][rt][nt][h * 2 + c] + (&bv[3][nt].x)[c];
                        float x1 = (c == 0) ? xv.x : xv.y;
                        float nr = x1 * sigm(sf) + tanha(lg) * sigm(lf);
                        v[c] = tanha(nr) * sigm(of);
                    }
                    if (L == 0) {
                        xout[ri][ch][nt] = pkh2(v[0], v[1]);
                    } else {
                        int row = row0 + ri * 8;
                        if (row < vcnt) {
                            *reinterpret_cast<float2*>(Out + (size_t)tokr[ri] * D
                                + ch * 16 + nt * 8 + lk * 2) = make_float2(v[0], v[1]);
                        }
                    }
                }
            }
        }
    }
}

// ---------------- main kernel ----------------
__global__ __launch_bounds__(NTHR, 2) void mpt_main(
    const float* __restrict__ X0,
    const float* __restrict__ Bv,
    float* __restrict__ Out)
{
    __shared__ __align__(16) float Bs_all[NLAYERS * NMAT * D];
    const int tid = threadIdx.x;

    // every thread computes block -> (expert, chunk, valid) itself
    int e = -1, loc = 0, vcnt = 0;
    {
        int b = blockIdx.x, acc = 0;
        #pragma unroll
        for (int e2 = 0; e2 < NE; e2++) {
            int cnt = (int)g_counts[e2];
            int pe = (cnt + TILE_M - 1) >> 7;
            if (e < 0 && b < acc + pe) {
                e = e2; loc = b - acc; vcnt = min(TILE_M, cnt - loc * TILE_M);
            }
            acc += pe;
        }
    }
    if (e < 0) return;

    // biases for both layers (the only shared data -> the only barrier)
    for (int i = tid; i < NLAYERS * NMAT * D; i += NTHR) {
        int l = i >> 9, j = (i >> 7) & 3, f = i & 127;
        Bs_all[i] = Bv[((size_t)(l * NMAT + j) * NE + e) * D + f];
    }

    const int lane = tid & 31, w = tid >> 5;
    const int lk = lane & 3, ln = lane >> 2;
    const int row0 = w * 32 + ln;

    unsigned tokr[4];
    #pragma unroll
    for (int ri = 0; ri < 4; ri++) {
        int r = row0 + ri * 8;
        tokr[ri] = g_list[(size_t)e * NTOK + loc * TILE_M + ((r < vcnt) ? r : 0)];
    }

    uint32_t xf[4][8][2], xn[4][8][2];
    #pragma unroll
    for (int ri = 0; ri < 4; ri++) {
        const float* xrow = X0 + (size_t)tokr[ri] * D + lk * 2;
        #pragma unroll
        for (int ks = 0; ks < 8; ks++) {
            #pragma unroll
            for (int s = 0; s < 2; s++) {
                float2 v = *reinterpret_cast<const float2*>(xrow + ks * 16 + s * 8);
                xf[ri][ks][s] = pkh2(v.x, v.y);
            }
        }
    }
    __syncthreads();   // biases visible; no further barriers anywhere

    do_layer<0>(xf, xn, Bs_all, e, lk, row0, tokr, vcnt, Out);
    do_layer<1>(xn, xf, Bs_all, e, lk, row0, tokr, vcnt, Out);
}

// ---------------- launch ----------------
extern "C" void kernel_launch(void* const* d_in, const int* in_sizes, int n_in,
                              void* d_out, int out_size)
{
    const int*   pos = (const int*)d_in[0];
    const float* X0  = (const float*)d_in[1];
    const float* W   = (const float*)d_in[2];
    const float* Bv  = (const float*)d_in[3];
    float*       Out = (float*)d_out;
    (void)in_sizes; (void)n_in; (void)out_size;

    prep_pack<<<(NLAYERS * NE * 8 * NMAT * 8 * 32) / 256, 256>>>(W);
    prep_scatter<<<NTOK / 256, 256>>>(pos);
    mpt_main<<<NBLK, NTHR>>>(X0, Bv, Out);
}

// round 15
// speedup vs baseline: 1.4069x; 1.4069x over previous
#include <cuda_runtime.h>
#include <cuda_fp16.h>
#include <cstdint>

#define NLAYERS 2
#define NMAT 4
#define NE 9
#define D 128
#define NTOK 65536
#define TILE_M 128
#define NBLK (NTOK / TILE_M + NE)     // 521
#define NTHR 128

#define SLAB_U4 1024                   // uint4 per 16-col chunk slab (16 KB)
#define OFF_BIAS 0                     // 2 layers x 4 mats x 128 floats = 4 KB
#define OFF_W    4096
#define OFF_XN   (OFF_W + 2 * SLAB_U4 * 16)        // 36864
#define SMEM_TOTAL (OFF_XN + NTHR * 64 * 4)        // 69632 B -> 3 CTAs/SM

// ---------------- device scratch ----------------
__device__ unsigned g_counts[NE];
__device__ unsigned g_list[NE * NTOK];             // per-expert arenas
// fragment-packed fp16 weights: [l][e][ch(8)][j(4)][ks(8)][lane(32)] uint4
__device__ uint4 g_Wp[NLAYERS * NE * 8 * NMAT * 8 * 32];

// ---------------- helpers ----------------
__device__ __forceinline__ float tanha(float v) {
    float r; asm("tanh.approx.f32 %0, %1;" : "=f"(r) : "f"(v)); return r;
}
__device__ __forceinline__ float sigm(float v) {
    return fmaf(0.5f, tanha(0.5f * v), 0.5f);
}
__device__ __forceinline__ uint32_t pkh2(float lo, float hi) {
    __half2 h = __floats2half2_rn(lo, hi);
    return *reinterpret_cast<uint32_t*>(&h);
}
__device__ __forceinline__ float2 uph2(uint32_t u) {
    __half2 h = *reinterpret_cast<__half2*>(&u);
    return __half22float2(h);
}
__device__ __forceinline__ void mma16(float* d, const uint32_t* a, uint32_t b0, uint32_t b1) {
    asm volatile(
        "mma.sync.aligned.m16n8k16.row.col.f32.f16.f16.f32 "
        "{%0,%1,%2,%3}, {%4,%5,%6,%7}, {%8,%9}, {%0,%1,%2,%3};"
        : "+f"(d[0]), "+f"(d[1]), "+f"(d[2]), "+f"(d[3])
        : "r"(a[0]), "r"(a[1]), "r"(a[2]), "r"(a[3]), "r"(b0), "r"(b1));
}
__device__ __forceinline__ void cpa16(uint32_t dst, const void* src) {
    asm volatile("cp.async.cg.shared.global [%0], [%1], 16;"
                 :: "r"(dst), "l"(__cvta_generic_to_global(src)) : "memory");
}

// ---------------- prep kernels (2 launches) ----------------
__global__ void prep_pack(const float* __restrict__ W) {
    if (blockIdx.x == 0 && threadIdx.x < NE) g_counts[threadIdx.x] = 0;
    int i = blockIdx.x * blockDim.x + threadIdx.x;   // 147456 threads
    int lane = i & 31;
    int ks   = (i >> 5) & 7;
    int j    = (i >> 8) & 3;
    int ch   = (i >> 10) & 7;
    int i2   = i >> 13;
    int e    = i2 % NE;
    int l    = i2 / NE;
    int lk = lane & 3, ln = lane >> 2;
    const float* src = W + ((size_t)(l * NMAT + j) * NE + e) * (D * D);
    int k0 = ks * 16 + lk * 2;
    int colA = ch * 16 + ln;
    int colB = colA + 8;
    uint4 v;
    v.x = pkh2(src[(k0    ) * D + colA], src[(k0 + 1) * D + colA]);
    v.y = pkh2(src[(k0 + 8) * D + colA], src[(k0 + 9) * D + colA]);
    v.z = pkh2(src[(k0    ) * D + colB], src[(k0 + 1) * D + colB]);
    v.w = pkh2(src[(k0 + 8) * D + colB], src[(k0 + 9) * D + colB]);
    g_Wp[i] = v;
}
__global__ void prep_scatter(const int* __restrict__ pos) {
    __shared__ unsigned sc[NE];
    __shared__ unsigned sb[NE];
    if (threadIdx.x < NE) sc[threadIdx.x] = 0;
    __syncthreads();
    int t = blockIdx.x * blockDim.x + threadIdx.x;
    int e = min(pos[t], NE - 1);
    unsigned my = atomicAdd(&sc[e], 1u);
    __syncthreads();
    if (threadIdx.x < NE) sb[threadIdx.x] = atomicAdd(&g_counts[threadIdx.x], sc[threadIdx.x]);
    __syncthreads();
    g_list[(size_t)e * NTOK + sb[e] + my] = (unsigned)t;
}

// ---------------- per-layer body ----------------
template<int L>
__device__ __forceinline__ void do_layer(
    uint32_t (&xin)[4][8][2], uint32_t* XnS,
    char* sm, uint32_t smW, int& buf, int e,
    int lane, int lk, int row0, const unsigned* tokr, int vcnt,
    float* __restrict__ Out, int tid)
{
    const float* Bs = (const float*)(sm + OFF_BIAS) + L * NMAT * D;

    #pragma unroll
    for (int ch = 0; ch < 8; ch++) {
        asm volatile("cp.async.wait_group 0;" ::: "memory");
        __syncthreads();   // slab[buf] ready; all warps done with slab[buf^1]
        int g = L * 8 + ch;
        if (g < 15) {
            int nl = (g + 1) >> 3, nch = (g + 1) & 7;
            const uint4* src = g_Wp + ((size_t)(nl * NE + e) * 8 + nch) * SLAB_U4;
            uint32_t dbase = smW + (buf ^ 1) * (SLAB_U4 * 16);
            #pragma unroll
            for (int i = 0; i < 8; i++) {
                int idx = tid + i * NTHR;
                cpa16(dbase + idx * 16, src + idx);
            }
            asm volatile("cp.async.commit_group;" ::: "memory");
        }

        // ---- GEMM: 32 rows/warp x 16 cols x 128 k, 4 matrices; A in registers ----
        float acc[4][2][2][4];
        #pragma unroll
        for (int m = 0; m < 4; m++)
            #pragma unroll
            for (int rt = 0; rt < 2; rt++)
                #pragma unroll
                for (int nt = 0; nt < 2; nt++)
                    #pragma unroll
                    for (int c = 0; c < 4; c++) acc[m][rt][nt][c] = 0.0f;

        const uint4* wb = (const uint4*)(sm + OFF_W) + buf * SLAB_U4 + lane;

        #pragma unroll
        for (int ks = 0; ks < 8; ks++) {
            uint32_t a0[4] = { xin[0][ks][0], xin[1][ks][0], xin[0][ks][1], xin[1][ks][1] };
            uint32_t a1[4] = { xin[2][ks][0], xin[3][ks][0], xin[2][ks][1], xin[3][ks][1] };
            #pragma unroll
            for (int m = 0; m < 4; m++) {
                uint4 bq = wb[(m * 8 + ks) * 32];
                mma16(acc[m][0][0], a0, bq.x, bq.y);
                mma16(acc[m][0][1], a0, bq.z, bq.w);
                mma16(acc[m][1][0], a1, bq.x, bq.y);
                mma16(acc[m][1][1], a1, bq.z, bq.w);
            }
        }

        // ---- gating (exact R11 arithmetic) ----
        float2 bv[4][2];
        #pragma unroll
        for (int m = 0; m < 4; m++)
            #pragma unroll
            for (int nt = 0; nt < 2; nt++)
                bv[m][nt] = *reinterpret_cast<const float2*>(
                    Bs + m * D + ch * 16 + nt * 8 + lk * 2);

        #pragma unroll
        for (int rt = 0; rt < 2; rt++) {
            #pragma unroll
            for (int h = 0; h < 2; h++) {
                int ri = rt * 2 + h;
                #pragma unroll
                for (int nt = 0; nt < 2; nt++) {
                    float2 xv = uph2(xin[ri][ch][nt]);
                    float v[2];
                    #pragma unroll
                    for (int c = 0; c < 2; c++) {
                        float sf = acc[0][rt][nt][h * 2 + c] + (&bv[0][nt].x)[c];
                        float lg = acc[1][rt][nt][h * 2 + c] + (&bv[1][nt].x)[c];
                        float lf = acc[2][rt][nt][h * 2 + c] + (&bv[2][nt].x)[c];
                        float of = acc[3][rt][nt][h * 2 + c] + (&bv[3][nt].x)[c];
                        float x1 = (c == 0) ? xv.x : xv.y;
                        float nr = x1 * sigm(sf) + tanha(lg) * sigm(lf);
                        v[c] = tanha(nr) * sigm(of);
                    }
                    if (L == 0) {
                        // stash layer-0 output in smem (own-thread data; no barrier needed)
                        XnS[(ch * 8 + ri * 2 + nt) * NTHR + tid] = pkh2(v[0], v[1]);
                    } else {
                        int row = row0 + ri * 8;
                        if (row < vcnt) {
                            *reinterpret_cast<float2*>(Out + (size_t)tokr[ri] * D
                                + ch * 16 + nt * 8 + lk * 2) = make_float2(v[0], v[1]);
                        }
                    }
                }
            }
        }
        buf ^= 1;
    }
}

// ---------------- main kernel ----------------
__global__ __launch_bounds__(NTHR, 3) void mpt_main(
    const float* __restrict__ X0,
    const float* __restrict__ Bv,
    float* __restrict__ Out)
{
    extern __shared__ __align__(16) char sm[];
    const uint32_t smW = (uint32_t)__cvta_generic_to_shared(sm + OFF_W);
    uint32_t* XnS = (uint32_t*)(sm + OFF_XN);
    const int tid = threadIdx.x;

    // every thread computes block -> (expert, chunk, valid) itself
    int e = -1, loc = 0, vcnt = 0;
    {
        int b = blockIdx.x, acc = 0;
        #pragma unroll
        for (int e2 = 0; e2 < NE; e2++) {
            int cnt = (int)g_counts[e2];
            int pe = (cnt + TILE_M - 1) >> 7;
            if (e < 0 && b < acc + pe) {
                e = e2; loc = b - acc; vcnt = min(TILE_M, cnt - loc * TILE_M);
            }
            acc += pe;
        }
    }
    if (e < 0) return;

    // prefetch (l=0, ch=0) slab into buffer 0
    {
        const uint4* src = g_Wp + (size_t)e * 8 * SLAB_U4;
        #pragma unroll
        for (int i = 0; i < 8; i++) {
            int idx = tid + i * NTHR;
            cpa16(smW + idx * 16, src + idx);
        }
        asm volatile("cp.async.commit_group;" ::: "memory");
    }

    // biases for both layers
    for (int i = tid; i < NLAYERS * NMAT * D; i += NTHR) {
        int l = i >> 9, j = (i >> 7) & 3, f = i & 127;
        ((float*)(sm + OFF_BIAS))[i] = Bv[((size_t)(l * NMAT + j) * NE + e) * D + f];
    }

    const int lane = tid & 31, w = tid >> 5;
    const int lk = lane & 3, ln = lane >> 2;
    const int row0 = w * 32 + ln;

    unsigned tokr[4];
    #pragma unroll
    for (int ri = 0; ri < 4; ri++) {
        int r = row0 + ri * 8;
        tokr[ri] = g_list[(size_t)e * NTOK + loc * TILE_M + ((r < vcnt) ? r : 0)];
    }

    uint32_t xf[4][8][2];
    #pragma unroll
    for (int ri = 0; ri < 4; ri++) {
        const float* xrow = X0 + (size_t)tokr[ri] * D + lk * 2;
        #pragma unroll
        for (int ks = 0; ks < 8; ks++) {
            #pragma unroll
            for (int s = 0; s < 2; s++) {
                float2 v = *reinterpret_cast<const float2*>(xrow + ks * 16 + s * 8);
                xf[ri][ks][s] = pkh2(v.x, v.y);
            }
        }
    }

    int buf = 0;
    do_layer<0>(xf, XnS, sm, smW, buf, e, lane, lk, row0, tokr, vcnt, Out, tid);

    // reload layer-0 output into the (now dead) xf registers
    #pragma unroll
    for (int ri = 0; ri < 4; ri++)
        #pragma unroll
        for (int ch = 0; ch < 8; ch++)
            #pragma unroll
            for (int nt = 0; nt < 2; nt++)
                xf[ri][ch][nt] = XnS[(ch * 8 + ri * 2 + nt) * NTHR + tid];

    do_layer<1>(xf, XnS, sm, smW, buf, e, lane, lk, row0, tokr, vcnt, Out, tid);
}

// ---------------- launch ----------------
extern "C" void kernel_launch(void* const* d_in, const int* in_sizes, int n_in,
                              void* d_out, int out_size)
{
    const int*   pos = (const int*)d_in[0];
    const float* X0  = (const float*)d_in[1];
    const float* W   = (const float*)d_in[2];
    const float* Bv  = (const float*)d_in[3];
    float*       Out = (float*)d_out;
    (void)in_sizes; (void)n_in; (void)out_size;

    cudaFuncSetAttribute(mpt_main, cudaFuncAttributeMaxDynamicSharedMemorySize, SMEM_TOTAL);

    prep_pack<<<(NLAYERS * NE * 8 * NMAT * 8 * 32) / 256, 256>>>(W);
    prep_scatter<<<NTOK / 256, 256>>>(pos);
    mpt_main<<<NBLK, NTHR, SMEM_TOTAL>>>(X0, Bv, Out);
}

// round 16
// speedup vs baseline: 1.4621x; 1.0392x over previous
#include <cuda_runtime.h>
#include <cuda_fp16.h>
#include <cstdint>

#define NLAYERS 2
#define NMAT 4
#define NE 9
#define D 128
#define NTOK 65536
#define TILE_M 128
#define NBLK (NTOK / TILE_M + NE)     // 521
#define NTHR 128

#define SLAB_U4 1024                   // uint4 per 16-col chunk slab (16 KB)
#define OFF_BIAS 0                     // 2 layers x 4 mats x 128 floats = 4 KB
#define OFF_W    4096
#define SMEM_TOTAL (OFF_W + 4 * SLAB_U4 * 16)   // 69632 B -> 2 CTAs/SM

// ---------------- device scratch ----------------
__device__ unsigned g_counts[NE];
__device__ unsigned g_list[NE * NTOK];             // per-expert arenas
// fragment-packed fp16 weights: [l][e][ch(8)][j(4)][ks(8)][lane(32)] uint4
__device__ uint4 g_Wp[NLAYERS * NE * 8 * NMAT * 8 * 32];

// ---------------- helpers ----------------
__device__ __forceinline__ float tanha(float v) {
    float r; asm("tanh.approx.f32 %0, %1;" : "=f"(r) : "f"(v)); return r;
}
__device__ __forceinline__ float sigm(float v) {
    return fmaf(0.5f, tanha(0.5f * v), 0.5f);
}
__device__ __forceinline__ uint32_t pkh2(float lo, float hi) {
    __half2 h = __floats2half2_rn(lo, hi);
    return *reinterpret_cast<uint32_t*>(&h);
}
__device__ __forceinline__ float2 uph2(uint32_t u) {
    __half2 h = *reinterpret_cast<__half2*>(&u);
    return __half22float2(h);
}
__device__ __forceinline__ void mma16(float* d, const uint32_t* a, uint32_t b0, uint32_t b1) {
    asm volatile(
        "mma.sync.aligned.m16n8k16.row.col.f32.f16.f16.f32 "
        "{%0,%1,%2,%3}, {%4,%5,%6,%7}, {%8,%9}, {%0,%1,%2,%3};"
        : "+f"(d[0]), "+f"(d[1]), "+f"(d[2]), "+f"(d[3])
        : "r"(a[0]), "r"(a[1]), "r"(a[2]), "r"(a[3]), "r"(b0), "r"(b1));
}
__device__ __forceinline__ void cpa16(uint32_t dst, const void* src) {
    asm volatile("cp.async.cg.shared.global [%0], [%1], 16;"
                 :: "r"(dst), "l"(__cvta_generic_to_global(src)) : "memory");
}

// ---------------- prep kernels (2 launches) ----------------
__global__ void prep_pack(const float* __restrict__ W) {
    if (blockIdx.x == 0 && threadIdx.x < NE) g_counts[threadIdx.x] = 0;
    int i = blockIdx.x * blockDim.x + threadIdx.x;   // 147456 threads
    int lane = i & 31;
    int ks   = (i >> 5) & 7;
    int j    = (i >> 8) & 3;
    int ch   = (i >> 10) & 7;
    int i2   = i >> 13;
    int e    = i2 % NE;
    int l    = i2 / NE;
    int lk = lane & 3, ln = lane >> 2;
    const float* src = W + ((size_t)(l * NMAT + j) * NE + e) * (D * D);
    int k0 = ks * 16 + lk * 2;
    int colA = ch * 16 + ln;
    int colB = colA + 8;
    uint4 v;
    v.x = pkh2(src[(k0    ) * D + colA], src[(k0 + 1) * D + colA]);
    v.y = pkh2(src[(k0 + 8) * D + colA], src[(k0 + 9) * D + colA]);
    v.z = pkh2(src[(k0    ) * D + colB], src[(k0 + 1) * D + colB]);
    v.w = pkh2(src[(k0 + 8) * D + colB], src[(k0 + 9) * D + colB]);
    g_Wp[i] = v;
}
__global__ void prep_scatter(const int* __restrict__ pos) {
    __shared__ unsigned sc[NE];
    __shared__ unsigned sb[NE];
    if (threadIdx.x < NE) sc[threadIdx.x] = 0;
    __syncthreads();
    int t = blockIdx.x * blockDim.x + threadIdx.x;
    int e = min(pos[t], NE - 1);
    unsigned my = atomicAdd(&sc[e], 1u);
    __syncthreads();
    if (threadIdx.x < NE) sb[threadIdx.x] = atomicAdd(&g_counts[threadIdx.x], sc[threadIdx.x]);
    __syncthreads();
    g_list[(size_t)e * NTOK + sb[e] + my] = (unsigned)t;
}

// ---------------- one chunk: GEMM + gating (exact R11 arithmetic) ----------------
template<int L>
__device__ __forceinline__ void do_chunk(
    int ch, int bufi,
    uint32_t (&xin)[4][8][2], uint32_t (&xout)[4][8][2],
    const char* sm, const float* Bs,
    int lane, int lk, int row0, const unsigned* tokr, int vcnt,
    float* __restrict__ Out)
{
    float acc[4][2][2][4];
    #pragma unroll
    for (int m = 0; m < 4; m++)
        #pragma unroll
        for (int rt = 0; rt < 2; rt++)
            #pragma unroll
            for (int nt = 0; nt < 2; nt++)
                #pragma unroll
                for (int c = 0; c < 4; c++) acc[m][rt][nt][c] = 0.0f;

    const uint4* wb = (const uint4*)(sm + OFF_W) + bufi * SLAB_U4 + lane;

    #pragma unroll
    for (int ks = 0; ks < 8; ks++) {
        uint32_t a0[4] = { xin[0][ks][0], xin[1][ks][0], xin[0][ks][1], xin[1][ks][1] };
        uint32_t a1[4] = { xin[2][ks][0], xin[3][ks][0], xin[2][ks][1], xin[3][ks][1] };
        #pragma unroll
        for (int m = 0; m < 4; m++) {
            uint4 bq = wb[(m * 8 + ks) * 32];
            mma16(acc[m][0][0], a0, bq.x, bq.y);
            mma16(acc[m][0][1], a0, bq.z, bq.w);
            mma16(acc[m][1][0], a1, bq.x, bq.y);
            mma16(acc[m][1][1], a1, bq.z, bq.w);
        }
    }

    float2 bv[4][2];
    #pragma unroll
    for (int m = 0; m < 4; m++)
        #pragma unroll
        for (int nt = 0; nt < 2; nt++)
            bv[m][nt] = *reinterpret_cast<const float2*>(
                Bs + m * D + ch * 16 + nt * 8 + lk * 2);

    #pragma unroll
    for (int rt = 0; rt < 2; rt++) {
        #pragma unroll
        for (int h = 0; h < 2; h++) {
            int ri = rt * 2 + h;
            #pragma unroll
            for (int nt = 0; nt < 2; nt++) {
                float2 xv = uph2(xin[ri][ch][nt]);
                float v[2];
                #pragma unroll
                for (int c = 0; c < 2; c++) {
                    float sf = acc[0][rt][nt][h * 2 + c] + (&bv[0][nt].x)[c];
                    float lg = acc[1][rt][nt][h * 2 + c] + (&bv[1][nt].x)[c];
                    float lf = acc[2][rt][nt][h * 2 + c] + (&bv[2][nt].x)[c];
                    float of = acc[3][rt][nt][h * 2 + c] + (&bv[3][nt].x)[c];
                    float x1 = (c == 0) ? xv.x : xv.y;
                    float nr = x1 * sigm(sf) + tanha(lg) * sigm(lf);
                    v[c] = tanha(nr) * sigm(of);
                }
                if (L == 0) {
                    xout[ri][ch][nt] = pkh2(v[0], v[1]);
                } else {
                    int row = row0 + ri * 8;
                    if (row < vcnt) {
                        *reinterpret_cast<float2*>(Out + (size_t)tokr[ri] * D
                            + ch * 16 + nt * 8 + lk * 2) = make_float2(v[0], v[1]);
                    }
                }
            }
        }
    }
}

// ---------------- per-layer: 4 pairs, 1 barrier per pair ----------------
template<int L>
__device__ __forceinline__ void do_layer(
    uint32_t (&xin)[4][8][2], uint32_t (&xout)[4][8][2],
    char* sm, uint32_t smW, int e,
    int lane, int lk, int row0, const unsigned* tokr, int vcnt,
    float* __restrict__ Out, int tid)
{
    const float* Bs = (const float*)(sm + OFF_BIAS) + L * NMAT * D;

    #pragma unroll
    for (int pc = 0; pc < 4; pc++) {
        const int gp = L * 8 + pc * 2;
        // current pair's slabs complete (this thread) ...
        asm volatile("cp.async.wait_group 0;" ::: "memory");
        // ... visible to all warps; and all warps done reading pair p-1 buffers
        __syncthreads();
        // prefetch next pair into pair p-1's buffers (one commit group for both)
        if (gp + 2 < 16) {
            #pragma unroll
            for (int t = 0; t < 2; t++) {
                int gg = gp + 2 + t;
                int nl = gg >> 3, nch = gg & 7;
                const uint4* src = g_Wp + ((size_t)(nl * NE + e) * 8 + nch) * SLAB_U4;
                uint32_t dbase = smW + (gg & 3) * (SLAB_U4 * 16);
                #pragma unroll
                for (int i = 0; i < 8; i++) {
                    int idx = tid + i * NTHR;
                    cpa16(dbase + idx * 16, src + idx);
                }
            }
            asm volatile("cp.async.commit_group;" ::: "memory");
        }
        // process the pair, no syncs inside
        do_chunk<L>(pc * 2 + 0, (gp + 0) & 3, xin, xout, sm, Bs,
                    lane, lk, row0, tokr, vcnt, Out);
        do_chunk<L>(pc * 2 + 1, (gp + 1) & 3, xin, xout, sm, Bs,
                    lane, lk, row0, tokr, vcnt, Out);
    }
}

// ---------------- main kernel ----------------
__global__ __launch_bounds__(NTHR, 2) void mpt_main(
    const float* __restrict__ X0,
    const float* __restrict__ Bv,
    float* __restrict__ Out)
{
    extern __shared__ __align__(16) char sm[];
    const uint32_t smW = (uint32_t)__cvta_generic_to_shared(sm + OFF_W);
    const int tid = threadIdx.x;

    // every thread computes block -> (expert, chunk, valid) itself
    int e = -1, loc = 0, vcnt = 0;
    {
        int b = blockIdx.x, acc = 0;
        #pragma unroll
        for (int e2 = 0; e2 < NE; e2++) {
            int cnt = (int)g_counts[e2];
            int pe = (cnt + TILE_M - 1) >> 7;
            if (e < 0 && b < acc + pe) {
                e = e2; loc = b - acc; vcnt = min(TILE_M, cnt - loc * TILE_M);
            }
            acc += pe;
        }
    }
    if (e < 0) return;

    // prologue: prefetch chunks 0,1 into buffers 0,1 (one group)
    {
        #pragma unroll
        for (int t = 0; t < 2; t++) {
            const uint4* src = g_Wp + ((size_t)e * 8 + t) * SLAB_U4;
            uint32_t dbase = smW + t * (SLAB_U4 * 16);
            #pragma unroll
            for (int i = 0; i < 8; i++) {
                int idx = tid + i * NTHR;
                cpa16(dbase + idx * 16, src + idx);
            }
        }
        asm volatile("cp.async.commit_group;" ::: "memory");
    }

    // biases for both layers
    for (int i = tid; i < NLAYERS * NMAT * D; i += NTHR) {
        int l = i >> 9, j = (i >> 7) & 3, f = i & 127;
        ((float*)(sm + OFF_BIAS))[i] = Bv[((size_t)(l * NMAT + j) * NE + e) * D + f];
    }

    const int lane = tid & 31, w = tid >> 5;
    const int lk = lane & 3, ln = lane >> 2;
    const int row0 = w * 32 + ln;

    unsigned tokr[4];
    #pragma unroll
    for (int ri = 0; ri < 4; ri++) {
        int r = row0 + ri * 8;
        tokr[ri] = g_list[(size_t)e * NTOK + loc * TILE_M + ((r < vcnt) ? r : 0)];
    }

    uint32_t xf[4][8][2], xn[4][8][2];
    #pragma unroll
    for (int ri = 0; ri < 4; ri++) {
        const float* xrow = X0 + (size_t)tokr[ri] * D + lk * 2;
        #pragma unroll
        for (int ks = 0; ks < 8; ks++) {
            #pragma unroll
            for (int s = 0; s < 2; s++) {
                float2 v = *reinterpret_cast<const float2*>(xrow + ks * 16 + s * 8);
                xf[ri][ks][s] = pkh2(v.x, v.y);
            }
        }
    }

    do_layer<0>(xf, xn, sm, smW, e, lane, lk, row0, tokr, vcnt, Out, tid);
    do_layer<1>(xn, xf, sm, smW, e, lane, lk, row0, tokr, vcnt, Out, tid);
}

// ---------------- launch ----------------
extern "C" void kernel_launch(void* const* d_in, const int* in_sizes, int n_in,
                              void* d_out, int out_size)
{
    const int*   pos = (const int*)d_in[0];
    const float* X0  = (const float*)d_in[1];
    const float* W   = (const float*)d_in[2];
    const float* Bv  = (const float*)d_in[3];
    float*       Out = (float*)d_out;
    (void)in_sizes; (void)n_in; (void)out_size;

    cudaFuncSetAttribute(mpt_main, cudaFuncAttributeMaxDynamicSharedMemorySize, SMEM_TOTAL);

    prep_pack<<<(NLAYERS * NE * 8 * NMAT * 8 * 32) / 256, 256>>>(W);
    prep_scatter<<<NTOK / 256, 256>>>(pos);
    mpt_main<<<NBLK, NTHR, SMEM_TOTAL>>>(X0, Bv, Out);
}